// round 16
// baseline (speedup 1.0000x reference)
#include <cuda_runtime.h>
#include <cuda_bf16.h>
#include <math.h>

#define B_TOT 16384
#define TX 30
#define TY 10
#define NA 32
#define NS 64
#define HV 128
#define MV 64
#define GE 128   // 4*NA
#define GP 256   // 4*NS

__device__ __align__(16) float g_a[(size_t)B_TOT * TX * (2 * NA)];   // 126 MB
__device__ int g_flag[256];      // zero-init; self-resetting (see decoder)
__device__ int g_consume[256];   // zero-init; 4 consumers per chunk

__device__ __forceinline__ float tanhapx(float x) {
    float y;
    asm("tanh.approx.f32 %0, %1;" : "=f"(y) : "f"(x));
    return y;
}
__device__ __forceinline__ float sigapx(float x) {
    return fmaf(tanhapx(0.5f * x), 0.5f, 0.5f);
}
__device__ __forceinline__ unsigned cvt_tf32(float x) {
    unsigned u;
    asm("cvt.rna.tf32.f32 %0, %1;" : "=r"(u) : "f"(x));
    return u;
}
__device__ __forceinline__ unsigned pack_bf16(float a, float b) {
    __nv_bfloat162 h = __floats2bfloat162_rn(a, b);
    return *(unsigned*)&h;
}
__device__ __forceinline__ void mma_tf32(float* d, const unsigned* a, unsigned b0, unsigned b1) {
    asm("mma.sync.aligned.m16n8k8.row.col.f32.tf32.tf32.f32 "
        "{%0,%1,%2,%3}, {%4,%5,%6,%7}, {%8,%9}, {%0,%1,%2,%3};"
        : "+f"(d[0]), "+f"(d[1]), "+f"(d[2]), "+f"(d[3])
        : "r"(a[0]), "r"(a[1]), "r"(a[2]), "r"(a[3]), "r"(b0), "r"(b1));
}
__device__ __forceinline__ void mma_bf16(float* d, unsigned a0, unsigned a1,
                                         unsigned a2, unsigned a3,
                                         unsigned b0, unsigned b1) {
    asm("mma.sync.aligned.m16n8k16.row.col.f32.bf16.bf16.f32 "
        "{%0,%1,%2,%3}, {%4,%5,%6,%7}, {%8,%9}, {%0,%1,%2,%3};"
        : "+f"(d[0]), "+f"(d[1]), "+f"(d[2]), "+f"(d[3])
        : "r"(a0), "r"(a1), "r"(a2), "r"(a3), "r"(b0), "r"(b1));
}

// ============================================================================
// Encoder v3 + PDL trigger + completion flags; final-step prefetch skipped.
// ============================================================================
#define EBE 64
#define ENC_THREADS 512
#define XST 68
#define HST 20
#define ENC_SMEM_BYTES ((2*2*64*XST + 2*2*64*HST) * 4)

#define BARD(d) asm volatile("bar.sync %0, %1;" :: "r"(1 + (d)), "r"(256) : "memory")

__global__ __launch_bounds__(ENC_THREADS, 1)
void encoder_fused(const float* __restrict__ X,
                   const float* __restrict__ W_ih_f, const float* __restrict__ W_hh_f,
                   const float* __restrict__ b_f,
                   const float* __restrict__ W_ih_r, const float* __restrict__ W_hh_r,
                   const float* __restrict__ b_r)
{
    cudaTriggerProgrammaticLaunchCompletion();

    const int b0  = blockIdx.x * EBE;
    const int tid = threadIdx.x;
    const int warp = tid >> 5, lane = tid & 31;
    const int g = lane >> 2, tg = lane & 3;
    const int dir = warp >> 3;
    const int wl  = warp & 7;
    const int wtid = tid & 255;

    extern __shared__ unsigned smu[];
    unsigned* xs  = smu;
    unsigned* hbf = xs + 2 * 2 * 64 * XST;

    const float* Wi = dir ? W_ih_r : W_ih_f;
    const float* Wh = dir ? W_hh_r : W_hh_f;
    const float* bb = dir ? b_r    : b_f;

    unsigned Bx[2][8][2], Bh[2][2][2];
    #pragma unroll
    for (int nt = 0; nt < 2; nt++) {
        int q  = wl * 16 + nt * 8 + g;
        int rr = (q & 3) * NA + (q >> 2);
        #pragma unroll
        for (int c = 0; c < 8; c++) {
            Bx[nt][c][0] = pack_bf16(Wi[rr * 128 + c * 16 + 2 * tg],
                                     Wi[rr * 128 + c * 16 + 2 * tg + 1]);
            Bx[nt][c][1] = pack_bf16(Wi[rr * 128 + c * 16 + 8 + 2 * tg],
                                     Wi[rr * 128 + c * 16 + 8 + 2 * tg + 1]);
        }
        #pragma unroll
        for (int c = 0; c < 2; c++) {
            Bh[nt][c][0] = pack_bf16(Wh[rr * 32 + c * 16 + 2 * tg],
                                     Wh[rr * 32 + c * 16 + 2 * tg + 1]);
            Bh[nt][c][1] = pack_bf16(Wh[rr * 32 + c * 16 + 8 + 2 * tg],
                                     Wh[rr * 32 + c * 16 + 8 + 2 * tg + 1]);
        }
    }
    float bcol[2][2];
    #pragma unroll
    for (int nt = 0; nt < 2; nt++) {
        int q0 = wl * 16 + nt * 8 + 2 * tg;
        bcol[nt][0] = bb[(q0 & 3) * NA + (q0 >> 2)];
        bcol[nt][1] = bb[((q0 + 1) & 3) * NA + ((q0 + 1) >> 2)];
    }
    float ccr[8];
    #pragma unroll
    for (int i = 0; i < 8; i++) ccr[i] = 0.0f;

    for (int i = tid; i < 2 * 2 * 64 * HST; i += ENC_THREADS) hbf[i] = 0u;
    #pragma unroll
    for (int ii = 0; ii < 8; ii++) {
        int flat = tid + ii * ENC_THREADS;
        int dd = flat >> 11, r = flat & 2047;
        int row = r >> 5, q = r & 31;
        int ts = dd ? (TX - 1) : 0;
        float4 v = *(const float4*)(X + ((size_t)(b0 + row) * TX + ts) * HV + q * 4);
        int c = q >> 2, jj0 = (q & 3) * 2;
        int p0 = (jj0 & 3) * 2 + (jj0 >> 2);
        int p1 = ((jj0 + 1) & 3) * 2 + ((jj0 + 1) >> 2);
        unsigned* dst = &xs[((0 * 2 + dd) * 64 + row) * XST + c * 8];
        dst[p0] = pack_bf16(v.x, v.y);
        dst[p1] = pack_bf16(v.z, v.w);
    }
    __syncthreads();

    const int hc  = wl >> 2;
    const int hjj = (wl & 3) * 2;
    const int hp0 = (hjj & 3) * 2 + (hjj >> 2);
    const int hp1 = ((hjj + 1) & 3) * 2 + ((hjj + 1) >> 2);

    int buf = 0;
    for (int t = 0; t < TX; t++) {
        const int par = t & 1;
        const int tt  = dir ? (TX - 1 - t) : t;
        const bool do_pre = (t < TX - 1);   // final step's prefetch is never read

        float4 xpre[8];
        if (do_pre) {
            const int tsn = dir ? (TX - 2 - t) : (t + 1);
            #pragma unroll
            for (int ii = 0; ii < 8; ii++) {
                int flat = wtid + ii * 256;
                int row = flat >> 5, q = flat & 31;
                xpre[ii] = *(const float4*)(X + ((size_t)(b0 + row) * TX + tsn) * HV + q * 4);
            }
        }

        #pragma unroll
        for (int half = 0; half < 2; half++) {
            float d[2][2][4];
            #pragma unroll
            for (int mi = 0; mi < 2; mi++)
                #pragma unroll
                for (int nt = 0; nt < 2; nt++)
                    #pragma unroll
                    for (int r = 0; r < 4; r++) d[mi][nt][r] = 0.0f;

            const unsigned* xbase = &xs[((buf * 2 + dir) * 64 + half * 32) * XST];
            #pragma unroll
            for (int c = 0; c < 8; c++) {
                unsigned a[2][4];
                #pragma unroll
                for (int mi = 0; mi < 2; mi++) {
                    uint2 lo = *(uint2*)&xbase[(mi * 16 + g) * XST + c * 8 + 2 * tg];
                    uint2 hi = *(uint2*)&xbase[(mi * 16 + 8 + g) * XST + c * 8 + 2 * tg];
                    a[mi][0] = lo.x; a[mi][1] = hi.x; a[mi][2] = lo.y; a[mi][3] = hi.y;
                }
                #pragma unroll
                for (int mi = 0; mi < 2; mi++) {
                    mma_bf16(d[mi][0], a[mi][0], a[mi][1], a[mi][2], a[mi][3],
                             Bx[0][c][0], Bx[0][c][1]);
                    mma_bf16(d[mi][1], a[mi][0], a[mi][1], a[mi][2], a[mi][3],
                             Bx[1][c][0], Bx[1][c][1]);
                }
            }
            const unsigned* hbase = &hbf[((par * 2 + dir) * 64 + half * 32) * HST];
            #pragma unroll
            for (int c = 0; c < 2; c++) {
                unsigned a[2][4];
                #pragma unroll
                for (int mi = 0; mi < 2; mi++) {
                    uint2 lo = *(uint2*)&hbase[(mi * 16 + g) * HST + c * 8 + 2 * tg];
                    uint2 hi = *(uint2*)&hbase[(mi * 16 + 8 + g) * HST + c * 8 + 2 * tg];
                    a[mi][0] = lo.x; a[mi][1] = hi.x; a[mi][2] = lo.y; a[mi][3] = hi.y;
                }
                #pragma unroll
                for (int mi = 0; mi < 2; mi++) {
                    mma_bf16(d[mi][0], a[mi][0], a[mi][1], a[mi][2], a[mi][3],
                             Bh[0][c][0], Bh[0][c][1]);
                    mma_bf16(d[mi][1], a[mi][0], a[mi][1], a[mi][2], a[mi][3],
                             Bh[1][c][0], Bh[1][c][1]);
                }
            }

            #pragma unroll
            for (int mi = 0; mi < 2; mi++) {
                float hh[2];
                #pragma unroll
                for (int nt = 0; nt < 2; nt++) {
                    d[mi][nt][0] += bcol[nt][0]; d[mi][nt][1] += bcol[nt][1];
                    d[mi][nt][2] += bcol[nt][0]; d[mi][nt][3] += bcol[nt][1];
                    float ex0 = __shfl_xor_sync(0xffffffffu, d[mi][nt][0], 1);
                    float ex1 = __shfl_xor_sync(0xffffffffu, d[mi][nt][1], 1);
                    float ex2 = __shfl_xor_sync(0xffffffffu, d[mi][nt][2], 1);
                    float ex3 = __shfl_xor_sync(0xffffffffu, d[mi][nt][3], 1);
                    bool odd = (tg & 1);
                    float zi = odd ? ex2       : d[mi][nt][0];
                    float zf = odd ? ex3       : d[mi][nt][1];
                    float zg = odd ? d[mi][nt][2] : ex0;
                    float zo = odd ? d[mi][nt][3] : ex1;
                    int ci = half * 4 + mi * 2 + nt;
                    float c = sigapx(zf) * ccr[ci] + sigapx(zi) * tanhapx(zg);
                    float h = sigapx(zo) * tanhapx(c);
                    ccr[ci] = c;
                    hh[nt] = h;
                }
                float r0 = __shfl_xor_sync(0xffffffffu, hh[0], 2);
                float r1 = __shfl_xor_sync(0xffffffffu, hh[1], 2);
                if (tg < 2) {
                    int row = half * 32 + mi * 16 + g + 8 * (tg & 1);
                    *(float4*)(g_a + ((size_t)(b0 + row) * TX + tt) * 64 + dir * 32 + wl * 4)
                        = make_float4(hh[0], r0, hh[1], r1);
                    unsigned* hd = &hbf[(((par ^ 1) * 2 + dir) * 64 + row) * HST + hc * 8];
                    hd[hp0] = pack_bf16(hh[0], r0);
                    hd[hp1] = pack_bf16(hh[1], r1);
                }
            }
        }

        if (do_pre) {
            #pragma unroll
            for (int ii = 0; ii < 8; ii++) {
                int flat = wtid + ii * 256;
                int row = flat >> 5, q = flat & 31;
                int c = q >> 2, jj0 = (q & 3) * 2;
                int p0 = (jj0 & 3) * 2 + (jj0 >> 2);
                int p1 = ((jj0 + 1) & 3) * 2 + ((jj0 + 1) >> 2);
                unsigned* dst = &xs[(((buf ^ 1) * 2 + dir) * 64 + row) * XST + c * 8];
                dst[p0] = pack_bf16(xpre[ii].x, xpre[ii].y);
                dst[p1] = pack_bf16(xpre[ii].z, xpre[ii].w);
            }
        }

        BARD(dir);
        buf ^= 1;
    }

    __syncthreads();
    if (tid == 0) {
        __threadfence();
        asm volatile("st.release.gpu.global.s32 [%0], %1;"
                     :: "l"(&g_flag[blockIdx.x]), "r"(1) : "memory");
    }
}

// ============================================================================
// Decoder v10 + self-resetting flags (4th consumer of each chunk resets flag
// and consume counter to 0 — restores initial state for the next graph replay
// without a clear kernel; safe because each consumer marks only after it has
// observed flag==1, and the next encoder run is stream-ordered after us).
// ============================================================================
#define DBE 16
#define DEC_THREADS 512
#define SABST 34
#define EAST 11
#define W1ST 68
#define SSST 68
#define INSPST 72
#define SCST 72

#define OFF_SAB   0
#define SZ_SAB    (DBE * 32 * SABST)
#define OFF_EA    (OFF_SAB + SZ_SAB)
#define SZ_EA_AL  5284
#define OFF_W1A   (OFF_EA + SZ_EA_AL)
#define OFF_W1S   (OFF_W1A + 640)
#define OFF_B1S   (OFF_W1S + 680)
#define OFF_W2S   (OFF_B1S + 16)
#define OFF_SS    (OFF_W2S + 16)
#define OFF_INSP  (OFF_SS + DBE * SSST)
#define OFF_SC    (OFF_INSP + DBE * INSPST)
#define OFF_ALPH  (OFF_SC + 2 * DBE * SCST)
#define DEC_UNITS (OFF_ALPH + DBE * 32)
#define DEC_SMEM_BYTES (DEC_UNITS * 4)

__global__ __launch_bounds__(DEC_THREADS, 1)
void decoder_kernel(const float* __restrict__ W1, const float* __restrict__ b1,
                    const float* __restrict__ W2, const float* __restrict__ b2,
                    const float* __restrict__ W_ih_p, const float* __restrict__ W_hh_p,
                    const float* __restrict__ b_p,
                    const float* __restrict__ Wo, const float* __restrict__ bo,
                    float* __restrict__ out)
{
    const int b0 = blockIdx.x * DBE;
    const int tid = threadIdx.x;
    const unsigned FULL = 0xffffffffu;

    extern __shared__ unsigned smw[];
    unsigned* sab = smw + OFF_SAB;
    float* ea   = (float*)(smw + OFF_EA);
    float* W1a  = (float*)(smw + OFF_W1A);
    float* W1s  = (float*)(smw + OFF_W1S);
    float* b1s  = (float*)(smw + OFF_B1S);
    float* W2s  = (float*)(smw + OFF_W2S);
    float* ss   = (float*)(smw + OFF_SS);
    unsigned* insp = smw + OFF_INSP;
    unsigned* scb  = smw + OFF_SC;
    float* alph = (float*)(smw + OFF_ALPH);

    const int warp = tid >> 5, lane = tid & 31;
    const int g = lane >> 2, tg = lane & 3;

    unsigned Bw[64];
    #pragma unroll
    for (int nt = 0; nt < 2; nt++) {
        int q  = warp * 16 + nt * 8 + g;
        int rr = (q & 3) * 64 + (q >> 2);
        #pragma unroll
        for (int c = 0; c < 8; c++) {
            Bw[(nt * 16 + c) * 2 + 0] = cvt_tf32(W_ih_p[rr * 64 + c * 8 + tg]);
            Bw[(nt * 16 + c) * 2 + 1] = cvt_tf32(W_ih_p[rr * 64 + c * 8 + tg + 4]);
        }
        #pragma unroll
        for (int c = 0; c < 8; c++) {
            Bw[(nt * 16 + (8 + c)) * 2 + 0] = cvt_tf32(W_hh_p[rr * 64 + c * 8 + tg]);
            Bw[(nt * 16 + (8 + c)) * 2 + 1] = cvt_tf32(W_hh_p[rr * 64 + c * 8 + tg + 4]);
        }
    }
    float bcol[2][2];
    #pragma unroll
    for (int nt = 0; nt < 2; nt++) {
        int q0 = warp * 16 + nt * 8 + 2 * tg;
        bcol[nt][0] = b_p[(q0 & 3) * 64 + (q0 >> 2)];
        bcol[nt][1] = b_p[((q0 + 1) & 3) * 64 + ((q0 + 1) >> 2)];
    }
    float ccr[2] = {0.0f, 0.0f};

    unsigned Bo[16];
    {
        int n = (warp & 7) * 8 + g;
        #pragma unroll
        for (int c = 0; c < 8; c++) {
            Bo[c * 2 + 0] = cvt_tf32(Wo[n * 64 + c * 8 + tg]);
            Bo[c * 2 + 1] = cvt_tf32(Wo[n * 64 + c * 8 + tg + 4]);
        }
    }
    const int m0 = (warp & 7) * 8 + 2 * tg;
    const float bo0 = bo[m0], bo1 = bo[m0 + 1];

    for (int i = tid; i < 640; i += DEC_THREADS) {
        int j = i / 64, d = i % 64;
        W1a[i]            = W1[j * 128 + d];
        W1s[j * W1ST + d] = W1[j * 128 + 64 + d];
    }
    if (tid < 10) { b1s[tid] = b1[tid]; W2s[tid] = W2[tid]; }
    for (int i = tid; i < DBE * SSST; i += DEC_THREADS) ss[i] = 0.0f;
    for (int i = tid; i < 2 * DBE * SCST; i += DEC_THREADS) scb[i] = 0u;
    const float b2v = b2[0];

    for (int i = tid; i < DBE * 2 * SABST; i += DEC_THREADS) {
        int e = i / (2 * SABST), r = i % (2 * SABST);
        sab[(e * 32 + 30) * SABST + r] = 0u;
    }

    // wait for encoder chunk; then register consumption (4th consumer resets)
    if (tid == 0) {
        const int chunk = blockIdx.x >> 2;
        int v;
        do {
            asm volatile("ld.acquire.gpu.global.s32 %0, [%1];"
                         : "=r"(v) : "l"(&g_flag[chunk]) : "memory");
            if (!v) __nanosleep(128);
        } while (!v);
        int c = atomicAdd(&g_consume[chunk], 1);
        if (c == 3) {                      // last of 4 consumers this run
            g_consume[chunk] = 0;
            asm volatile("st.relaxed.gpu.global.s32 [%0], %1;"
                         :: "l"(&g_flag[chunk]), "r"(0) : "memory");
        }
    }
    __syncthreads();

    for (int i = tid; i < DBE * TX * 16; i += DEC_THREADS) {
        int e = i / (TX * 16);
        int r = i % (TX * 16);
        int tx = r / 16, d4 = r % 16;
        float4 v = *(const float4*)(g_a + ((size_t)(b0 + e) * TX + tx) * (2 * NA) + d4 * 4);
        sab[(e * 32 + tx) * SABST + 2 * d4]     = pack_bf16(v.x, v.y);
        sab[(e * 32 + tx) * SABST + 2 * d4 + 1] = pack_bf16(v.z, v.w);
    }
    __syncthreads();

    if (tid < DBE * TX) {
        int e = tid / TX, tx = tid % TX;
        float acc[10];
        #pragma unroll
        for (int j = 0; j < 10; j++) acc[j] = 0.0f;
        #pragma unroll 4
        for (int d2 = 0; d2 < 32; d2++) {
            unsigned av = sab[(e * 32 + tx) * SABST + d2];
            float f0 = __uint_as_float(av << 16);
            float f1 = __uint_as_float(av & 0xffff0000u);
            #pragma unroll
            for (int j = 0; j < 10; j++)
                acc[j] += f0 * W1a[j * 64 + 2 * d2] + f1 * W1a[j * 64 + 2 * d2 + 1];
        }
        #pragma unroll
        for (int j = 0; j < 10; j++) ea[(e * TX + tx) * EAST + j] = acc[j];
    }
    __syncthreads();

    for (int t = 0; t < TY; t++) {
        const unsigned* scr = scb + (t & 1) * (DBE * SCST);
        unsigned* scw = scb + ((t + 1) & 1) * (DBE * SCST);

        // ---- A+B+C: warp e = attention ----
        {
            const int e = warp;
            float accA = 0.0f;
            if (lane < 20) {
                int j = lane >> 1, half = lane & 1;
                const float4* sp = (const float4*)&ss[e * SSST + half * 32];
                const float4* wp = (const float4*)&W1s[j * W1ST + half * 32];
                float a0 = 0.0f, a1 = 0.0f;
                #pragma unroll
                for (int q = 0; q < 8; q += 2) {
                    float4 s0 = sp[q],     w0 = wp[q];
                    float4 s1 = sp[q + 1], w1 = wp[q + 1];
                    a0 += s0.x * w0.x + s0.y * w0.y + s0.z * w0.z + s0.w * w0.w;
                    a1 += s1.x * w1.x + s1.y * w1.y + s1.z * w1.z + s1.w * w1.w;
                }
                accA = a0 + a1;
            }
            accA += __shfl_xor_sync(FULL, accA, 1);
            if (lane < 20) accA += b1s[lane >> 1];

            int txc = (lane < TX) ? lane : 0;
            float esj[10], eav[10], th[10];
            #pragma unroll
            for (int j = 0; j < 10; j++) esj[j] = __shfl_sync(FULL, accA, 2 * j);
            #pragma unroll
            for (int j = 0; j < 10; j++) eav[j] = ea[(e * TX + txc) * EAST + j];
            #pragma unroll
            for (int j = 0; j < 10; j++) th[j] = tanhapx(eav[j] + esj[j]);
            float s0 = b2v, s1 = 0.0f;
            #pragma unroll
            for (int j = 0; j < 10; j += 2) {
                s0 += th[j]     * W2s[j];
                s1 += th[j + 1] * W2s[j + 1];
            }
            float en = fmaxf(s0 + s1, 0.0f);
            float ex = (lane < TX) ? __expf(en) : 0.0f;
            float sum = ex;
            #pragma unroll
            for (int o = 16; o; o >>= 1) sum += __shfl_xor_sync(FULL, sum, o);
            alph[e * 32 + lane] = ex * __fdividef(1.0f, sum);
        }
        __syncwarp();

        // ---- D: 4-way split ctx accumulators ----
        {
            const int e = tid >> 5, d2 = tid & 31;
            const float4* ap = (const float4*)&alph[e * 32];
            float c0a = 0.0f, c0b = 0.0f, c1a = 0.0f, c1b = 0.0f;
            #pragma unroll
            for (int c = 0; c < 4; c++) {
                float4 a4 = ap[c];
                unsigned v0 = sab[(e * 32 + 4 * c + 0) * SABST + d2];
                unsigned v1 = sab[(e * 32 + 4 * c + 1) * SABST + d2];
                unsigned v2 = sab[(e * 32 + 4 * c + 2) * SABST + d2];
                unsigned v3 = sab[(e * 32 + 4 * c + 3) * SABST + d2];
                c0a += a4.x * __uint_as_float(v0 << 16)
                     + a4.y * __uint_as_float(v1 << 16)
                     + a4.z * __uint_as_float(v2 << 16)
                     + a4.w * __uint_as_float(v3 << 16);
                c1a += a4.x * __uint_as_float(v0 & 0xffff0000u)
                     + a4.y * __uint_as_float(v1 & 0xffff0000u)
                     + a4.z * __uint_as_float(v2 & 0xffff0000u)
                     + a4.w * __uint_as_float(v3 & 0xffff0000u);
            }
            #pragma unroll
            for (int c = 4; c < 8; c++) {
                float4 a4 = ap[c];
                unsigned v0 = sab[(e * 32 + 4 * c + 0) * SABST + d2];
                unsigned v1 = sab[(e * 32 + 4 * c + 1) * SABST + d2];
                unsigned v2 = sab[(e * 32 + 4 * c + 2) * SABST + d2];
                unsigned v3 = sab[(e * 32 + 4 * c + 3) * SABST + d2];
                c0b += a4.x * __uint_as_float(v0 << 16)
                     + a4.y * __uint_as_float(v1 << 16)
                     + a4.z * __uint_as_float(v2 << 16)
                     + a4.w * __uint_as_float(v3 << 16);
                c1b += a4.x * __uint_as_float(v0 & 0xffff0000u)
                     + a4.y * __uint_as_float(v1 & 0xffff0000u)
                     + a4.z * __uint_as_float(v2 & 0xffff0000u)
                     + a4.w * __uint_as_float(v3 & 0xffff0000u);
            }
            float ctx0 = c0a + c0b, ctx1 = c1a + c1b;
            int d0 = 2 * d2;
            int c0 = d0 >> 3, jj0 = d0 & 7;
            int p0 = (jj0 & 3) * 2 + (jj0 >> 2);
            int p1 = ((jj0 + 1) & 3) * 2 + ((jj0 + 1) >> 2);
            insp[e * INSPST + c0 * 8 + p0] = cvt_tf32(ctx0);
            insp[e * INSPST + c0 * 8 + p1] = cvt_tf32(ctx1);
        }
        __syncthreads();

        // ---- E+F fused: gate mma + in-register cell ----
        {
            float dd[2][4];
            #pragma unroll
            for (int nt = 0; nt < 2; nt++)
                #pragma unroll
                for (int r = 0; r < 4; r++) dd[nt][r] = 0.0f;
            #pragma unroll
            for (int c = 0; c < 8; c++) {
                uint2 va = *(uint2*)&insp[g * INSPST + c * 8 + 2 * tg];
                uint2 vb = *(uint2*)&insp[(g + 8) * INSPST + c * 8 + 2 * tg];
                unsigned a[4] = {va.x, vb.x, va.y, vb.y};
                mma_tf32(dd[0], a, Bw[(0 * 16 + c) * 2], Bw[(0 * 16 + c) * 2 + 1]);
                mma_tf32(dd[1], a, Bw[(1 * 16 + c) * 2], Bw[(1 * 16 + c) * 2 + 1]);
            }
            #pragma unroll
            for (int c = 0; c < 8; c++) {
                uint2 va = *(uint2*)&scr[g * SCST + c * 8 + 2 * tg];
                uint2 vb = *(uint2*)&scr[(g + 8) * SCST + c * 8 + 2 * tg];
                unsigned a[4] = {va.x, vb.x, va.y, vb.y};
                mma_tf32(dd[0], a, Bw[(0 * 16 + 8 + c) * 2], Bw[(0 * 16 + 8 + c) * 2 + 1]);
                mma_tf32(dd[1], a, Bw[(1 * 16 + 8 + c) * 2], Bw[(1 * 16 + 8 + c) * 2 + 1]);
            }
            float hh[2];
            #pragma unroll
            for (int nt = 0; nt < 2; nt++) {
                dd[nt][0] += bcol[nt][0]; dd[nt][1] += bcol[nt][1];
                dd[nt][2] += bcol[nt][0]; dd[nt][3] += bcol[nt][1];
                float ex0 = __shfl_xor_sync(FULL, dd[nt][0], 1);
                float ex1 = __shfl_xor_sync(FULL, dd[nt][1], 1);
                float ex2 = __shfl_xor_sync(FULL, dd[nt][2], 1);
                float ex3 = __shfl_xor_sync(FULL, dd[nt][3], 1);
                bool odd = (tg & 1);
                float zi = odd ? ex2        : dd[nt][0];
                float zf = odd ? ex3        : dd[nt][1];
                float zg = odd ? dd[nt][2]  : ex0;
                float zo = odd ? dd[nt][3]  : ex1;
                float c = sigapx(zf) * ccr[nt] + sigapx(zi) * tanhapx(zg);
                float h = sigapx(zo) * tanhapx(c);
                ccr[nt] = c;
                hh[nt] = h;
            }
            float r0 = __shfl_xor_sync(FULL, hh[0], 2);
            float r1 = __shfl_xor_sync(FULL, hh[1], 2);
            if (tg < 2) {
                int e = g + 8 * (tg & 1);
                *(float4*)&ss[e * SSST + warp * 4] = make_float4(hh[0], r0, hh[1], r1);
                unsigned* sc = &scw[e * SCST + (warp >> 1) * 8 + (warp & 1)];
                sc[0] = cvt_tf32(hh[0]);
                sc[2] = cvt_tf32(r0);
                sc[4] = cvt_tf32(hh[1]);
                sc[6] = cvt_tf32(r1);
            }
        }
        __syncthreads();

        // ---- OUT: warps 0-7 via tf32 mma ----
        if (warp < 8) {
            float dd[4] = {0.0f, 0.0f, 0.0f, 0.0f};
            #pragma unroll
            for (int c = 0; c < 8; c++) {
                uint2 va = *(uint2*)&scw[g * SCST + c * 8 + 2 * tg];
                uint2 vb = *(uint2*)&scw[(g + 8) * SCST + c * 8 + 2 * tg];
                unsigned a[4] = {va.x, vb.x, va.y, vb.y};
                mma_tf32(dd, a, Bo[c * 2], Bo[c * 2 + 1]);
            }
            *(float2*)(out + ((size_t)(b0 + g) * TY + t) * MV + m0)
                = make_float2(dd[0] + bo0, dd[1] + bo1);
            *(float2*)(out + ((size_t)(b0 + g + 8) * TY + t) * MV + m0)
                = make_float2(dd[2] + bo0, dd[3] + bo1);
        }
    }
}

// ============================================================================
extern "C" void kernel_launch(void* const* d_in, const int* in_sizes, int n_in,
                              void* d_out, int out_size)
{
    const float* X      = (const float*)d_in[0];
    const float* W_ih_f = (const float*)d_in[1];
    const float* W_hh_f = (const float*)d_in[2];
    const float* b_f    = (const float*)d_in[3];
    const float* W_ih_r = (const float*)d_in[4];
    const float* W_hh_r = (const float*)d_in[5];
    const float* b_r    = (const float*)d_in[6];
    const float* W1     = (const float*)d_in[7];
    const float* b1     = (const float*)d_in[8];
    const float* W2     = (const float*)d_in[9];
    const float* b2     = (const float*)d_in[10];
    const float* W_ih_p = (const float*)d_in[11];
    const float* W_hh_p = (const float*)d_in[12];
    const float* b_p    = (const float*)d_in[13];
    const float* Wo     = (const float*)d_in[14];
    const float* bo     = (const float*)d_in[15];
    float* out = (float*)d_out;

    cudaFuncSetAttribute(encoder_fused,  cudaFuncAttributeMaxDynamicSharedMemorySize, ENC_SMEM_BYTES);
    cudaFuncSetAttribute(decoder_kernel, cudaFuncAttributeMaxDynamicSharedMemorySize, DEC_SMEM_BYTES);

    encoder_fused<<<B_TOT / EBE, ENC_THREADS, ENC_SMEM_BYTES>>>(
        X, W_ih_f, W_hh_f, b_f, W_ih_r, W_hh_r, b_r);

    cudaLaunchConfig_t cfg = {};
    cfg.gridDim = dim3(B_TOT / DBE, 1, 1);
    cfg.blockDim = dim3(DEC_THREADS, 1, 1);
    cfg.dynamicSmemBytes = DEC_SMEM_BYTES;
    cfg.stream = 0;
    cudaLaunchAttribute attr[1];
    attr[0].id = cudaLaunchAttributeProgrammaticStreamSerialization;
    attr[0].val.programmaticStreamSerializationAllowed = 1;
    cfg.attrs = attr;
    cfg.numAttrs = 1;
    cudaLaunchKernelEx(&cfg, decoder_kernel, W1, b1, W2, b2,
                       W_ih_p, W_hh_p, b_p, Wo, bo, out);
}

// round 17
// speedup vs baseline: 1.0212x; 1.0212x over previous
#include <cuda_runtime.h>
#include <cuda_bf16.h>
#include <math.h>

#define B_TOT 16384
#define TX 30
#define TY 10
#define NA 32
#define NS 64
#define HV 128
#define MV 64
#define GE 128   // 4*NA
#define GP 256   // 4*NS

__device__ __align__(16) float g_a[(size_t)B_TOT * TX * (2 * NA)];   // 126 MB
__device__ int g_flag[256];      // zero-init; self-resetting (see decoder)
__device__ int g_consume[256];   // zero-init; 4 consumers per chunk

__device__ __forceinline__ float tanhapx(float x) {
    float y;
    asm("tanh.approx.f32 %0, %1;" : "=f"(y) : "f"(x));
    return y;
}
__device__ __forceinline__ float sigapx(float x) {
    return fmaf(tanhapx(0.5f * x), 0.5f, 0.5f);
}
__device__ __forceinline__ unsigned cvt_tf32(float x) {
    unsigned u;
    asm("cvt.rna.tf32.f32 %0, %1;" : "=r"(u) : "f"(x));
    return u;
}
__device__ __forceinline__ unsigned pack_bf16(float a, float b) {
    __nv_bfloat162 h = __floats2bfloat162_rn(a, b);
    return *(unsigned*)&h;
}
__device__ __forceinline__ void mma_tf32(float* d, const unsigned* a, unsigned b0, unsigned b1) {
    asm("mma.sync.aligned.m16n8k8.row.col.f32.tf32.tf32.f32 "
        "{%0,%1,%2,%3}, {%4,%5,%6,%7}, {%8,%9}, {%0,%1,%2,%3};"
        : "+f"(d[0]), "+f"(d[1]), "+f"(d[2]), "+f"(d[3])
        : "r"(a[0]), "r"(a[1]), "r"(a[2]), "r"(a[3]), "r"(b0), "r"(b1));
}
__device__ __forceinline__ void mma_bf16(float* d, unsigned a0, unsigned a1,
                                         unsigned a2, unsigned a3,
                                         unsigned b0, unsigned b1) {
    asm("mma.sync.aligned.m16n8k16.row.col.f32.bf16.bf16.f32 "
        "{%0,%1,%2,%3}, {%4,%5,%6,%7}, {%8,%9}, {%0,%1,%2,%3};"
        : "+f"(d[0]), "+f"(d[1]), "+f"(d[2]), "+f"(d[3])
        : "r"(a0), "r"(a1), "r"(a2), "r"(a3), "r"(b0), "r"(b1));
}

// ============================================================================
// Encoder v3 + PDL trigger + completion flags (byte-identical to R15:
// unconditional prefetch every step — the R16 conditional guard regressed it)
// ============================================================================
#define EBE 64
#define ENC_THREADS 512
#define XST 68
#define HST 20
#define ENC_SMEM_BYTES ((2*2*64*XST + 2*2*64*HST) * 4)

#define BARD(d) asm volatile("bar.sync %0, %1;" :: "r"(1 + (d)), "r"(256) : "memory")

__global__ __launch_bounds__(ENC_THREADS, 1)
void encoder_fused(const float* __restrict__ X,
                   const float* __restrict__ W_ih_f, const float* __restrict__ W_hh_f,
                   const float* __restrict__ b_f,
                   const float* __restrict__ W_ih_r, const float* __restrict__ W_hh_r,
                   const float* __restrict__ b_r)
{
    cudaTriggerProgrammaticLaunchCompletion();

    const int b0  = blockIdx.x * EBE;
    const int tid = threadIdx.x;
    const int warp = tid >> 5, lane = tid & 31;
    const int g = lane >> 2, tg = lane & 3;
    const int dir = warp >> 3;
    const int wl  = warp & 7;
    const int wtid = tid & 255;

    extern __shared__ unsigned smu[];
    unsigned* xs  = smu;
    unsigned* hbf = xs + 2 * 2 * 64 * XST;

    const float* Wi = dir ? W_ih_r : W_ih_f;
    const float* Wh = dir ? W_hh_r : W_hh_f;
    const float* bb = dir ? b_r    : b_f;

    unsigned Bx[2][8][2], Bh[2][2][2];
    #pragma unroll
    for (int nt = 0; nt < 2; nt++) {
        int q  = wl * 16 + nt * 8 + g;
        int rr = (q & 3) * NA + (q >> 2);
        #pragma unroll
        for (int c = 0; c < 8; c++) {
            Bx[nt][c][0] = pack_bf16(Wi[rr * 128 + c * 16 + 2 * tg],
                                     Wi[rr * 128 + c * 16 + 2 * tg + 1]);
            Bx[nt][c][1] = pack_bf16(Wi[rr * 128 + c * 16 + 8 + 2 * tg],
                                     Wi[rr * 128 + c * 16 + 8 + 2 * tg + 1]);
        }
        #pragma unroll
        for (int c = 0; c < 2; c++) {
            Bh[nt][c][0] = pack_bf16(Wh[rr * 32 + c * 16 + 2 * tg],
                                     Wh[rr * 32 + c * 16 + 2 * tg + 1]);
            Bh[nt][c][1] = pack_bf16(Wh[rr * 32 + c * 16 + 8 + 2 * tg],
                                     Wh[rr * 32 + c * 16 + 8 + 2 * tg + 1]);
        }
    }
    float bcol[2][2];
    #pragma unroll
    for (int nt = 0; nt < 2; nt++) {
        int q0 = wl * 16 + nt * 8 + 2 * tg;
        bcol[nt][0] = bb[(q0 & 3) * NA + (q0 >> 2)];
        bcol[nt][1] = bb[((q0 + 1) & 3) * NA + ((q0 + 1) >> 2)];
    }
    float ccr[8];
    #pragma unroll
    for (int i = 0; i < 8; i++) ccr[i] = 0.0f;

    for (int i = tid; i < 2 * 2 * 64 * HST; i += ENC_THREADS) hbf[i] = 0u;
    #pragma unroll
    for (int ii = 0; ii < 8; ii++) {
        int flat = tid + ii * ENC_THREADS;
        int dd = flat >> 11, r = flat & 2047;
        int row = r >> 5, q = r & 31;
        int ts = dd ? (TX - 1) : 0;
        float4 v = *(const float4*)(X + ((size_t)(b0 + row) * TX + ts) * HV + q * 4);
        int c = q >> 2, jj0 = (q & 3) * 2;
        int p0 = (jj0 & 3) * 2 + (jj0 >> 2);
        int p1 = ((jj0 + 1) & 3) * 2 + ((jj0 + 1) >> 2);
        unsigned* dst = &xs[((0 * 2 + dd) * 64 + row) * XST + c * 8];
        dst[p0] = pack_bf16(v.x, v.y);
        dst[p1] = pack_bf16(v.z, v.w);
    }
    __syncthreads();

    const int hc  = wl >> 2;
    const int hjj = (wl & 3) * 2;
    const int hp0 = (hjj & 3) * 2 + (hjj >> 2);
    const int hp1 = ((hjj + 1) & 3) * 2 + ((hjj + 1) >> 2);

    int buf = 0;
    for (int t = 0; t < TX; t++) {
        const int par = t & 1;
        const int tt  = dir ? (TX - 1 - t) : t;

        float4 xpre[8];
        const int tsn = dir ? max(TX - 2 - t, 0) : min(t + 1, TX - 1);
        #pragma unroll
        for (int ii = 0; ii < 8; ii++) {
            int flat = wtid + ii * 256;
            int row = flat >> 5, q = flat & 31;
            xpre[ii] = *(const float4*)(X + ((size_t)(b0 + row) * TX + tsn) * HV + q * 4);
        }

        #pragma unroll
        for (int half = 0; half < 2; half++) {
            float d[2][2][4];
            #pragma unroll
            for (int mi = 0; mi < 2; mi++)
                #pragma unroll
                for (int nt = 0; nt < 2; nt++)
                    #pragma unroll
                    for (int r = 0; r < 4; r++) d[mi][nt][r] = 0.0f;

            const unsigned* xbase = &xs[((buf * 2 + dir) * 64 + half * 32) * XST];
            #pragma unroll
            for (int c = 0; c < 8; c++) {
                unsigned a[2][4];
                #pragma unroll
                for (int mi = 0; mi < 2; mi++) {
                    uint2 lo = *(uint2*)&xbase[(mi * 16 + g) * XST + c * 8 + 2 * tg];
                    uint2 hi = *(uint2*)&xbase[(mi * 16 + 8 + g) * XST + c * 8 + 2 * tg];
                    a[mi][0] = lo.x; a[mi][1] = hi.x; a[mi][2] = lo.y; a[mi][3] = hi.y;
                }
                #pragma unroll
                for (int mi = 0; mi < 2; mi++) {
                    mma_bf16(d[mi][0], a[mi][0], a[mi][1], a[mi][2], a[mi][3],
                             Bx[0][c][0], Bx[0][c][1]);
                    mma_bf16(d[mi][1], a[mi][0], a[mi][1], a[mi][2], a[mi][3],
                             Bx[1][c][0], Bx[1][c][1]);
                }
            }
            const unsigned* hbase = &hbf[((par * 2 + dir) * 64 + half * 32) * HST];
            #pragma unroll
            for (int c = 0; c < 2; c++) {
                unsigned a[2][4];
                #pragma unroll
                for (int mi = 0; mi < 2; mi++) {
                    uint2 lo = *(uint2*)&hbase[(mi * 16 + g) * HST + c * 8 + 2 * tg];
                    uint2 hi = *(uint2*)&hbase[(mi * 16 + 8 + g) * HST + c * 8 + 2 * tg];
                    a[mi][0] = lo.x; a[mi][1] = hi.x; a[mi][2] = lo.y; a[mi][3] = hi.y;
                }
                #pragma unroll
                for (int mi = 0; mi < 2; mi++) {
                    mma_bf16(d[mi][0], a[mi][0], a[mi][1], a[mi][2], a[mi][3],
                             Bh[0][c][0], Bh[0][c][1]);
                    mma_bf16(d[mi][1], a[mi][0], a[mi][1], a[mi][2], a[mi][3],
                             Bh[1][c][0], Bh[1][c][1]);
                }
            }

            #pragma unroll
            for (int mi = 0; mi < 2; mi++) {
                float hh[2];
                #pragma unroll
                for (int nt = 0; nt < 2; nt++) {
                    d[mi][nt][0] += bcol[nt][0]; d[mi][nt][1] += bcol[nt][1];
                    d[mi][nt][2] += bcol[nt][0]; d[mi][nt][3] += bcol[nt][1];
                    float ex0 = __shfl_xor_sync(0xffffffffu, d[mi][nt][0], 1);
                    float ex1 = __shfl_xor_sync(0xffffffffu, d[mi][nt][1], 1);
                    float ex2 = __shfl_xor_sync(0xffffffffu, d[mi][nt][2], 1);
                    float ex3 = __shfl_xor_sync(0xffffffffu, d[mi][nt][3], 1);
                    bool odd = (tg & 1);
                    float zi = odd ? ex2       : d[mi][nt][0];
                    float zf = odd ? ex3       : d[mi][nt][1];
                    float zg = odd ? d[mi][nt][2] : ex0;
                    float zo = odd ? d[mi][nt][3] : ex1;
                    int ci = half * 4 + mi * 2 + nt;
                    float c = sigapx(zf) * ccr[ci] + sigapx(zi) * tanhapx(zg);
                    float h = sigapx(zo) * tanhapx(c);
                    ccr[ci] = c;
                    hh[nt] = h;
                }
                float r0 = __shfl_xor_sync(0xffffffffu, hh[0], 2);
                float r1 = __shfl_xor_sync(0xffffffffu, hh[1], 2);
                if (tg < 2) {
                    int row = half * 32 + mi * 16 + g + 8 * (tg & 1);
                    *(float4*)(g_a + ((size_t)(b0 + row) * TX + tt) * 64 + dir * 32 + wl * 4)
                        = make_float4(hh[0], r0, hh[1], r1);
                    unsigned* hd = &hbf[(((par ^ 1) * 2 + dir) * 64 + row) * HST + hc * 8];
                    hd[hp0] = pack_bf16(hh[0], r0);
                    hd[hp1] = pack_bf16(hh[1], r1);
                }
            }
        }

        #pragma unroll
        for (int ii = 0; ii < 8; ii++) {
            int flat = wtid + ii * 256;
            int row = flat >> 5, q = flat & 31;
            int c = q >> 2, jj0 = (q & 3) * 2;
            int p0 = (jj0 & 3) * 2 + (jj0 >> 2);
            int p1 = ((jj0 + 1) & 3) * 2 + ((jj0 + 1) >> 2);
            unsigned* dst = &xs[(((buf ^ 1) * 2 + dir) * 64 + row) * XST + c * 8];
            dst[p0] = pack_bf16(xpre[ii].x, xpre[ii].y);
            dst[p1] = pack_bf16(xpre[ii].z, xpre[ii].w);
        }

        BARD(dir);
        buf ^= 1;
    }

    __syncthreads();
    if (tid == 0) {
        __threadfence();
        asm volatile("st.release.gpu.global.s32 [%0], %1;"
                     :: "l"(&g_flag[blockIdx.x]), "r"(1) : "memory");
    }
}

// ============================================================================
// Decoder v10 + self-resetting flags: the 4th consumer of each chunk resets
// flag and counter, restoring initial state for the next graph replay with no
// clear kernel. All 4 consumers exit their spin before the reset can fire;
// the next replay's encoder is stream-ordered after this kernel completes.
// ============================================================================
#define DBE 16
#define DEC_THREADS 512
#define SABST 34
#define EAST 11
#define W1ST 68
#define SSST 68
#define INSPST 72
#define SCST 72

#define OFF_SAB   0
#define SZ_SAB    (DBE * 32 * SABST)
#define OFF_EA    (OFF_SAB + SZ_SAB)
#define SZ_EA_AL  5284
#define OFF_W1A   (OFF_EA + SZ_EA_AL)
#define OFF_W1S   (OFF_W1A + 640)
#define OFF_B1S   (OFF_W1S + 680)
#define OFF_W2S   (OFF_B1S + 16)
#define OFF_SS    (OFF_W2S + 16)
#define OFF_INSP  (OFF_SS + DBE * SSST)
#define OFF_SC    (OFF_INSP + DBE * INSPST)
#define OFF_ALPH  (OFF_SC + 2 * DBE * SCST)
#define DEC_UNITS (OFF_ALPH + DBE * 32)
#define DEC_SMEM_BYTES (DEC_UNITS * 4)

__global__ __launch_bounds__(DEC_THREADS, 1)
void decoder_kernel(const float* __restrict__ W1, const float* __restrict__ b1,
                    const float* __restrict__ W2, const float* __restrict__ b2,
                    const float* __restrict__ W_ih_p, const float* __restrict__ W_hh_p,
                    const float* __restrict__ b_p,
                    const float* __restrict__ Wo, const float* __restrict__ bo,
                    float* __restrict__ out)
{
    const int b0 = blockIdx.x * DBE;
    const int tid = threadIdx.x;
    const unsigned FULL = 0xffffffffu;

    extern __shared__ unsigned smw[];
    unsigned* sab = smw + OFF_SAB;
    float* ea   = (float*)(smw + OFF_EA);
    float* W1a  = (float*)(smw + OFF_W1A);
    float* W1s  = (float*)(smw + OFF_W1S);
    float* b1s  = (float*)(smw + OFF_B1S);
    float* W2s  = (float*)(smw + OFF_W2S);
    float* ss   = (float*)(smw + OFF_SS);
    unsigned* insp = smw + OFF_INSP;
    unsigned* scb  = smw + OFF_SC;
    float* alph = (float*)(smw + OFF_ALPH);

    const int warp = tid >> 5, lane = tid & 31;
    const int g = lane >> 2, tg = lane & 3;

    unsigned Bw[64];
    #pragma unroll
    for (int nt = 0; nt < 2; nt++) {
        int q  = warp * 16 + nt * 8 + g;
        int rr = (q & 3) * 64 + (q >> 2);
        #pragma unroll
        for (int c = 0; c < 8; c++) {
            Bw[(nt * 16 + c) * 2 + 0] = cvt_tf32(W_ih_p[rr * 64 + c * 8 + tg]);
            Bw[(nt * 16 + c) * 2 + 1] = cvt_tf32(W_ih_p[rr * 64 + c * 8 + tg + 4]);
        }
        #pragma unroll
        for (int c = 0; c < 8; c++) {
            Bw[(nt * 16 + (8 + c)) * 2 + 0] = cvt_tf32(W_hh_p[rr * 64 + c * 8 + tg]);
            Bw[(nt * 16 + (8 + c)) * 2 + 1] = cvt_tf32(W_hh_p[rr * 64 + c * 8 + tg + 4]);
        }
    }
    float bcol[2][2];
    #pragma unroll
    for (int nt = 0; nt < 2; nt++) {
        int q0 = warp * 16 + nt * 8 + 2 * tg;
        bcol[nt][0] = b_p[(q0 & 3) * 64 + (q0 >> 2)];
        bcol[nt][1] = b_p[((q0 + 1) & 3) * 64 + ((q0 + 1) >> 2)];
    }
    float ccr[2] = {0.0f, 0.0f};

    unsigned Bo[16];
    {
        int n = (warp & 7) * 8 + g;
        #pragma unroll
        for (int c = 0; c < 8; c++) {
            Bo[c * 2 + 0] = cvt_tf32(Wo[n * 64 + c * 8 + tg]);
            Bo[c * 2 + 1] = cvt_tf32(Wo[n * 64 + c * 8 + tg + 4]);
        }
    }
    const int m0 = (warp & 7) * 8 + 2 * tg;
    const float bo0 = bo[m0], bo1 = bo[m0 + 1];

    for (int i = tid; i < 640; i += DEC_THREADS) {
        int j = i / 64, d = i % 64;
        W1a[i]            = W1[j * 128 + d];
        W1s[j * W1ST + d] = W1[j * 128 + 64 + d];
    }
    if (tid < 10) { b1s[tid] = b1[tid]; W2s[tid] = W2[tid]; }
    for (int i = tid; i < DBE * SSST; i += DEC_THREADS) ss[i] = 0.0f;
    for (int i = tid; i < 2 * DBE * SCST; i += DEC_THREADS) scb[i] = 0u;
    const float b2v = b2[0];

    for (int i = tid; i < DBE * 2 * SABST; i += DEC_THREADS) {
        int e = i / (2 * SABST), r = i % (2 * SABST);
        sab[(e * 32 + 30) * SABST + r] = 0u;
    }

    // wait for encoder chunk; 4th consumer resets flag + counter for the
    // next graph replay (no clear kernel needed)
    if (tid == 0) {
        const int chunk = blockIdx.x >> 2;
        int v;
        do {
            asm volatile("ld.acquire.gpu.global.s32 %0, [%1];"
                         : "=r"(v) : "l"(&g_flag[chunk]) : "memory");
            if (!v) __nanosleep(128);
        } while (!v);
        int c = atomicAdd(&g_consume[chunk], 1);
        if (c == 3) {
            g_consume[chunk] = 0;
            asm volatile("st.relaxed.gpu.global.s32 [%0], %1;"
                         :: "l"(&g_flag[chunk]), "r"(0) : "memory");
        }
    }
    __syncthreads();

    for (int i = tid; i < DBE * TX * 16; i += DEC_THREADS) {
        int e = i / (TX * 16);
        int r = i % (TX * 16);
        int tx = r / 16, d4 = r % 16;
        float4 v = *(const float4*)(g_a + ((size_t)(b0 + e) * TX + tx) * (2 * NA) + d4 * 4);
        sab[(e * 32 + tx) * SABST + 2 * d4]     = pack_bf16(v.x, v.y);
        sab[(e * 32 + tx) * SABST + 2 * d4 + 1] = pack_bf16(v.z, v.w);
    }
    __syncthreads();

    if (tid < DBE * TX) {
        int e = tid / TX, tx = tid % TX;
        float acc[10];
        #pragma unroll
        for (int j = 0; j < 10; j++) acc[j] = 0.0f;
        #pragma unroll 4
        for (int d2 = 0; d2 < 32; d2++) {
            unsigned av = sab[(e * 32 + tx) * SABST + d2];
            float f0 = __uint_as_float(av << 16);
            float f1 = __uint_as_float(av & 0xffff0000u);
            #pragma unroll
            for (int j = 0; j < 10; j++)
                acc[j] += f0 * W1a[j * 64 + 2 * d2] + f1 * W1a[j * 64 + 2 * d2 + 1];
        }
        #pragma unroll
        for (int j = 0; j < 10; j++) ea[(e * TX + tx) * EAST + j] = acc[j];
    }
    __syncthreads();

    for (int t = 0; t < TY; t++) {
        const unsigned* scr = scb + (t & 1) * (DBE * SCST);
        unsigned* scw = scb + ((t + 1) & 1) * (DBE * SCST);

        // ---- A+B+C: warp e = attention ----
        {
            const int e = warp;
            float accA = 0.0f;
            if (lane < 20) {
                int j = lane >> 1, half = lane & 1;
                const float4* sp = (const float4*)&ss[e * SSST + half * 32];
                const float4* wp = (const float4*)&W1s[j * W1ST + half * 32];
                float a0 = 0.0f, a1 = 0.0f;
                #pragma unroll
                for (int q = 0; q < 8; q += 2) {
                    float4 s0 = sp[q],     w0 = wp[q];
                    float4 s1 = sp[q + 1], w1 = wp[q + 1];
                    a0 += s0.x * w0.x + s0.y * w0.y + s0.z * w0.z + s0.w * w0.w;
                    a1 += s1.x * w1.x + s1.y * w1.y + s1.z * w1.z + s1.w * w1.w;
                }
                accA = a0 + a1;
            }
            accA += __shfl_xor_sync(FULL, accA, 1);
            if (lane < 20) accA += b1s[lane >> 1];

            int txc = (lane < TX) ? lane : 0;
            float esj[10], eav[10], th[10];
            #pragma unroll
            for (int j = 0; j < 10; j++) esj[j] = __shfl_sync(FULL, accA, 2 * j);
            #pragma unroll
            for (int j = 0; j < 10; j++) eav[j] = ea[(e * TX + txc) * EAST + j];
            #pragma unroll
            for (int j = 0; j < 10; j++) th[j] = tanhapx(eav[j] + esj[j]);
            float s0 = b2v, s1 = 0.0f;
            #pragma unroll
            for (int j = 0; j < 10; j += 2) {
                s0 += th[j]     * W2s[j];
                s1 += th[j + 1] * W2s[j + 1];
            }
            float en = fmaxf(s0 + s1, 0.0f);
            float ex = (lane < TX) ? __expf(en) : 0.0f;
            float sum = ex;
            #pragma unroll
            for (int o = 16; o; o >>= 1) sum += __shfl_xor_sync(FULL, sum, o);
            alph[e * 32 + lane] = ex * __fdividef(1.0f, sum);
        }
        __syncwarp();

        // ---- D: 4-way split ctx accumulators ----
        {
            const int e = tid >> 5, d2 = tid & 31;
            const float4* ap = (const float4*)&alph[e * 32];
            float c0a = 0.0f, c0b = 0.0f, c1a = 0.0f, c1b = 0.0f;
            #pragma unroll
            for (int c = 0; c < 4; c++) {
                float4 a4 = ap[c];
                unsigned v0 = sab[(e * 32 + 4 * c + 0) * SABST + d2];
                unsigned v1 = sab[(e * 32 + 4 * c + 1) * SABST + d2];
                unsigned v2 = sab[(e * 32 + 4 * c + 2) * SABST + d2];
                unsigned v3 = sab[(e * 32 + 4 * c + 3) * SABST + d2];
                c0a += a4.x * __uint_as_float(v0 << 16)
                     + a4.y * __uint_as_float(v1 << 16)
                     + a4.z * __uint_as_float(v2 << 16)
                     + a4.w * __uint_as_float(v3 << 16);
                c1a += a4.x * __uint_as_float(v0 & 0xffff0000u)
                     + a4.y * __uint_as_float(v1 & 0xffff0000u)
                     + a4.z * __uint_as_float(v2 & 0xffff0000u)
                     + a4.w * __uint_as_float(v3 & 0xffff0000u);
            }
            #pragma unroll
            for (int c = 4; c < 8; c++) {
                float4 a4 = ap[c];
                unsigned v0 = sab[(e * 32 + 4 * c + 0) * SABST + d2];
                unsigned v1 = sab[(e * 32 + 4 * c + 1) * SABST + d2];
                unsigned v2 = sab[(e * 32 + 4 * c + 2) * SABST + d2];
                unsigned v3 = sab[(e * 32 + 4 * c + 3) * SABST + d2];
                c0b += a4.x * __uint_as_float(v0 << 16)
                     + a4.y * __uint_as_float(v1 << 16)
                     + a4.z * __uint_as_float(v2 << 16)
                     + a4.w * __uint_as_float(v3 << 16);
                c1b += a4.x * __uint_as_float(v0 & 0xffff0000u)
                     + a4.y * __uint_as_float(v1 & 0xffff0000u)
                     + a4.z * __uint_as_float(v2 & 0xffff0000u)
                     + a4.w * __uint_as_float(v3 & 0xffff0000u);
            }
            float ctx0 = c0a + c0b, ctx1 = c1a + c1b;
            int d0 = 2 * d2;
            int c0 = d0 >> 3, jj0 = d0 & 7;
            int p0 = (jj0 & 3) * 2 + (jj0 >> 2);
            int p1 = ((jj0 + 1) & 3) * 2 + ((jj0 + 1) >> 2);
            insp[e * INSPST + c0 * 8 + p0] = cvt_tf32(ctx0);
            insp[e * INSPST + c0 * 8 + p1] = cvt_tf32(ctx1);
        }
        __syncthreads();

        // ---- E+F fused: gate mma + in-register cell ----
        {
            float dd[2][4];
            #pragma unroll
            for (int nt = 0; nt < 2; nt++)
                #pragma unroll
                for (int r = 0; r < 4; r++) dd[nt][r] = 0.0f;
            #pragma unroll
            for (int c = 0; c < 8; c++) {
                uint2 va = *(uint2*)&insp[g * INSPST + c * 8 + 2 * tg];
                uint2 vb = *(uint2*)&insp[(g + 8) * INSPST + c * 8 + 2 * tg];
                unsigned a[4] = {va.x, vb.x, va.y, vb.y};
                mma_tf32(dd[0], a, Bw[(0 * 16 + c) * 2], Bw[(0 * 16 + c) * 2 + 1]);
                mma_tf32(dd[1], a, Bw[(1 * 16 + c) * 2], Bw[(1 * 16 + c) * 2 + 1]);
            }
            #pragma unroll
            for (int c = 0; c < 8; c++) {
                uint2 va = *(uint2*)&scr[g * SCST + c * 8 + 2 * tg];
                uint2 vb = *(uint2*)&scr[(g + 8) * SCST + c * 8 + 2 * tg];
                unsigned a[4] = {va.x, vb.x, va.y, vb.y};
                mma_tf32(dd[0], a, Bw[(0 * 16 + 8 + c) * 2], Bw[(0 * 16 + 8 + c) * 2 + 1]);
                mma_tf32(dd[1], a, Bw[(1 * 16 + 8 + c) * 2], Bw[(1 * 16 + 8 + c) * 2 + 1]);
            }
            float hh[2];
            #pragma unroll
            for (int nt = 0; nt < 2; nt++) {
                dd[nt][0] += bcol[nt][0]; dd[nt][1] += bcol[nt][1];
                dd[nt][2] += bcol[nt][0]; dd[nt][3] += bcol[nt][1];
                float ex0 = __shfl_xor_sync(FULL, dd[nt][0], 1);
                float ex1 = __shfl_xor_sync(FULL, dd[nt][1], 1);
                float ex2 = __shfl_xor_sync(FULL, dd[nt][2], 1);
                float ex3 = __shfl_xor_sync(FULL, dd[nt][3], 1);
                bool odd = (tg & 1);
                float zi = odd ? ex2        : dd[nt][0];
                float zf = odd ? ex3        : dd[nt][1];
                float zg = odd ? dd[nt][2]  : ex0;
                float zo = odd ? dd[nt][3]  : ex1;
                float c = sigapx(zf) * ccr[nt] + sigapx(zi) * tanhapx(zg);
                float h = sigapx(zo) * tanhapx(c);
                ccr[nt] = c;
                hh[nt] = h;
            }
            float r0 = __shfl_xor_sync(FULL, hh[0], 2);
            float r1 = __shfl_xor_sync(FULL, hh[1], 2);
            if (tg < 2) {
                int e = g + 8 * (tg & 1);
                *(float4*)&ss[e * SSST + warp * 4] = make_float4(hh[0], r0, hh[1], r1);
                unsigned* sc = &scw[e * SCST + (warp >> 1) * 8 + (warp & 1)];
                sc[0] = cvt_tf32(hh[0]);
                sc[2] = cvt_tf32(r0);
                sc[4] = cvt_tf32(hh[1]);
                sc[6] = cvt_tf32(r1);
            }
        }
        __syncthreads();

        // ---- OUT: warps 0-7 via tf32 mma ----
        if (warp < 8) {
            float dd[4] = {0.0f, 0.0f, 0.0f, 0.0f};
            #pragma unroll
            for (int c = 0; c < 8; c++) {
                uint2 va = *(uint2*)&scw[g * SCST + c * 8 + 2 * tg];
                uint2 vb = *(uint2*)&scw[(g + 8) * SCST + c * 8 + 2 * tg];
                unsigned a[4] = {va.x, vb.x, va.y, vb.y};
                mma_tf32(dd, a, Bo[c * 2], Bo[c * 2 + 1]);
            }
            *(float2*)(out + ((size_t)(b0 + g) * TY + t) * MV + m0)
                = make_float2(dd[0] + bo0, dd[1] + bo1);
            *(float2*)(out + ((size_t)(b0 + g + 8) * TY + t) * MV + m0)
                = make_float2(dd[2] + bo0, dd[3] + bo1);
        }
    }
}

// ============================================================================
extern "C" void kernel_launch(void* const* d_in, const int* in_sizes, int n_in,
                              void* d_out, int out_size)
{
    const float* X      = (const float*)d_in[0];
    const float* W_ih_f = (const float*)d_in[1];
    const float* W_hh_f = (const float*)d_in[2];
    const float* b_f    = (const float*)d_in[3];
    const float* W_ih_r = (const float*)d_in[4];
    const float* W_hh_r = (const float*)d_in[5];
    const float* b_r    = (const float*)d_in[6];
    const float* W1     = (const float*)d_in[7];
    const float* b1     = (const float*)d_in[8];
    const float* W2     = (const float*)d_in[9];
    const float* b2     = (const float*)d_in[10];
    const float* W_ih_p = (const float*)d_in[11];
    const float* W_hh_p = (const float*)d_in[12];
    const float* b_p    = (const float*)d_in[13];
    const float* Wo     = (const float*)d_in[14];
    const float* bo     = (const float*)d_in[15];
    float* out = (float*)d_out;

    cudaFuncSetAttribute(encoder_fused,  cudaFuncAttributeMaxDynamicSharedMemorySize, ENC_SMEM_BYTES);
    cudaFuncSetAttribute(decoder_kernel, cudaFuncAttributeMaxDynamicSharedMemorySize, DEC_SMEM_BYTES);

    encoder_fused<<<B_TOT / EBE, ENC_THREADS, ENC_SMEM_BYTES>>>(
        X, W_ih_f, W_hh_f, b_f, W_ih_r, W_hh_r, b_r);

    cudaLaunchConfig_t cfg = {};
    cfg.gridDim = dim3(B_TOT / DBE, 1, 1);
    cfg.blockDim = dim3(DEC_THREADS, 1, 1);
    cfg.dynamicSmemBytes = DEC_SMEM_BYTES;
    cfg.stream = 0;
    cudaLaunchAttribute attr[1];
    attr[0].id = cudaLaunchAttributeProgrammaticStreamSerialization;
    attr[0].val.programmaticStreamSerializationAllowed = 1;
    cfg.attrs = attr;
    cfg.numAttrs = 1;
    cudaLaunchKernelEx(&cfg, decoder_kernel, W1, b1, W2, b2,
                       W_ih_p, W_hh_p, b_p, Wo, bo, out);
}